// round 13
// baseline (speedup 1.0000x reference)
#include <cuda_runtime.h>
#include <cuda_fp16.h>
#include <math.h>
#include <stdint.h>

#define Nn  4
#define Cc  768
#define Ww  2048
#define Hh  12
#define Dd  64
#define Gg  4
#define CPG 192
#define LOG2E 1.4426950408889634f
#define ONES_H2 0x3C003C00u   // half2(1.0, 1.0)

// fp16 scratch for projected Q/K/V in [n, h, w, d] layout. Q pre-scaled by
// 0.125 * log2(e) so attention scores are directly in log2 domain.
__device__ __half g_Q[(size_t)Nn*Hh*Ww*Dd];
__device__ __half g_K[(size_t)Nn*Hh*Ww*Dd];
__device__ __half g_V[(size_t)Nn*Hh*Ww*Dd];

// ---------------- shared PTX helpers ----------------
__device__ __forceinline__ void ldsm_x4(uint32_t& r0, uint32_t& r1,
                                        uint32_t& r2, uint32_t& r3, uint32_t a) {
    asm volatile("ldmatrix.sync.aligned.m8n8.x4.shared.b16 {%0,%1,%2,%3}, [%4];\n"
                 : "=r"(r0), "=r"(r1), "=r"(r2), "=r"(r3) : "r"(a));
}
__device__ __forceinline__ void ldsm_x4_t(uint32_t& r0, uint32_t& r1,
                                          uint32_t& r2, uint32_t& r3, uint32_t a) {
    asm volatile("ldmatrix.sync.aligned.m8n8.x4.trans.shared.b16 {%0,%1,%2,%3}, [%4];\n"
                 : "=r"(r0), "=r"(r1), "=r"(r2), "=r"(r3) : "r"(a));
}
__device__ __forceinline__ void mma16816(float* c, const uint32_t* a,
                                         uint32_t b0, uint32_t b1) {
    asm volatile("mma.sync.aligned.m16n8k16.row.col.f32.f16.f16.f32 "
                 "{%0,%1,%2,%3}, {%4,%5,%6,%7}, {%8,%9}, {%0,%1,%2,%3};\n"
                 : "+f"(c[0]), "+f"(c[1]), "+f"(c[2]), "+f"(c[3])
                 : "r"(a[0]), "r"(a[1]), "r"(a[2]), "r"(a[3]), "r"(b0), "r"(b1));
}
__device__ __forceinline__ uint32_t pack_h2(float lo, float hi) {
    uint32_t r;
    asm("cvt.rn.f16x2.f32 %0, %1, %2;" : "=r"(r) : "f"(hi), "f"(lo));
    return r;
}
// exp2 on two packed halves in one MUFU op
__device__ __forceinline__ uint32_t ex2h2(uint32_t x) {
    uint32_t y;
    asm("ex2.approx.f16x2 %0, %1;" : "=r"(y) : "r"(x));
    return y;
}
__device__ __forceinline__ void cp16(uint32_t dst, const void* src) {
    asm volatile("cp.async.cg.shared.global [%0], [%1], 16;\n" :: "r"(dst), "l"(src));
}
__device__ __forceinline__ void cp_commit() {
    asm volatile("cp.async.commit_group;\n");
}
__device__ __forceinline__ void cp_wait0() {
    asm volatile("cp.async.wait_group 0;\n");
}

// ---------------------------------------------------------------------------
// Kernel 1: grouped 1x1 conv as HMMA GEMM (unchanged, proven).
// ---------------------------------------------------------------------------
__global__ __launch_bounds__(256) void qkv_kernel(
    const float* __restrict__ x,
    const float* __restrict__ wq, const float* __restrict__ bq,
    const float* __restrict__ wk, const float* __restrict__ bk,
    const float* __restrict__ wv, const float* __restrict__ bv)
{
    __shared__ alignas(16) __half Xs[2][32][136];
    __shared__ alignas(16) __half Ws[2][64][40];
    __shared__ float bias_s[64];

    const int wt = blockIdx.x;
    const int ot = blockIdx.y;
    const int z  = blockIdx.z;
    const int t  = z % 3;
    const int ng = z / 3;
    const int n  = ng >> 2, g = ng & 3;

    const float* W = (t == 0) ? wq : (t == 1) ? wk : wv;
    const float* B = (t == 0) ? bq : (t == 1) ? bk : bv;
    __half* dst    = (t == 0) ? g_Q : (t == 1) ? g_K : g_V;

    const int tid  = threadIdx.x;
    const int warp = tid >> 5;
    const int lane = tid & 31;
    const int tq   = lane >> 3;
    const int li   = lane & 7;
    const int m0w  = warp * 16;

    const int cgbase = g * CPG + ot * 64;
    const int h = cgbase >> 6;
    const int w0 = wt * 128;
    const float* Wg = W + (size_t)g * CPG * CPG + (size_t)(ot * 64) * CPG;
    const float* Xg = x + ((size_t)n * Cc + g * CPG) * Ww;

    if (tid < 64) bias_s[tid] = B[cgbase + tid];

    const int xc  = tid >> 3;
    const int xw  = (tid & 7) * 16;
    const int woc = tid >> 2;
    const int wc  = (tid & 3) * 8;

    float4 xr[4], wr[2];
    {
        const float* src = &Xg[(size_t)xc * Ww + w0 + xw];
        xr[0] = *(const float4*)&src[0];
        xr[1] = *(const float4*)&src[4];
        xr[2] = *(const float4*)&src[8];
        xr[3] = *(const float4*)&src[12];
        const float* ws = &Wg[(size_t)woc * CPG + wc];
        wr[0] = *(const float4*)&ws[0];
        wr[1] = *(const float4*)&ws[4];
    }

    float acc[8][4];
#pragma unroll
    for (int j = 0; j < 8; j++)
#pragma unroll
        for (int c = 0; c < 4; c++) acc[j][c] = 0.f;

    for (int it = 0; it < 6; it++) {
        const int cur = it & 1;
        {
            __align__(16) __half2 hh[8];
            hh[0] = __floats2half2_rn(xr[0].x, xr[0].y);
            hh[1] = __floats2half2_rn(xr[0].z, xr[0].w);
            hh[2] = __floats2half2_rn(xr[1].x, xr[1].y);
            hh[3] = __floats2half2_rn(xr[1].z, xr[1].w);
            hh[4] = __floats2half2_rn(xr[2].x, xr[2].y);
            hh[5] = __floats2half2_rn(xr[2].z, xr[2].w);
            hh[6] = __floats2half2_rn(xr[3].x, xr[3].y);
            hh[7] = __floats2half2_rn(xr[3].z, xr[3].w);
            *(uint4*)&Xs[cur][xc][xw]     = ((uint4*)hh)[0];
            *(uint4*)&Xs[cur][xc][xw + 8] = ((uint4*)hh)[1];
            __align__(16) __half2 wh[4];
            wh[0] = __floats2half2_rn(wr[0].x, wr[0].y);
            wh[1] = __floats2half2_rn(wr[0].z, wr[0].w);
            wh[2] = __floats2half2_rn(wr[1].x, wr[1].y);
            wh[3] = __floats2half2_rn(wr[1].z, wr[1].w);
            *(uint4*)&Ws[cur][woc][wc] = *(uint4*)wh;
        }
        __syncthreads();
        if (it + 1 < 6) {
            const int k0 = (it + 1) * 32;
            const float* src = &Xg[(size_t)(k0 + xc) * Ww + w0 + xw];
            xr[0] = *(const float4*)&src[0];
            xr[1] = *(const float4*)&src[4];
            xr[2] = *(const float4*)&src[8];
            xr[3] = *(const float4*)&src[12];
            const float* ws = &Wg[(size_t)woc * CPG + (it + 1) * 32 + wc];
            wr[0] = *(const float4*)&ws[0];
            wr[1] = *(const float4*)&ws[4];
        }

#pragma unroll
        for (int kk = 0; kk < 2; kk++) {
            uint32_t af[4];
            {
                const int row = kk * 16 + (tq >> 1) * 8 + li;
                const int col = m0w + (tq & 1) * 8;
                uint32_t a = (uint32_t)__cvta_generic_to_shared(&Xs[cur][row][col]);
                ldsm_x4_t(af[0], af[1], af[2], af[3], a);
            }
            uint32_t b[16];
#pragma unroll
            for (int p = 0; p < 4; p++) {
                const int row = (p * 2 + (tq >> 1)) * 8 + li;
                const int col = kk * 16 + (tq & 1) * 8;
                uint32_t a = (uint32_t)__cvta_generic_to_shared(&Ws[cur][row][col]);
                ldsm_x4(b[p * 4], b[p * 4 + 1], b[p * 4 + 2], b[p * 4 + 3], a);
            }
#pragma unroll
            for (int j = 0; j < 8; j++) {
                const int base = (j >> 1) * 4 + (j & 1) * 2;
                mma16816(acc[j], af, b[base], b[base + 1]);
            }
        }
    }

    const float qs = (t == 0) ? (0.125f * LOG2E) : 1.0f;
    __half* outp = dst + (((size_t)n * Hh + h) * Ww + w0) * Dd;
    const int r0 = m0w + (lane >> 2);
    const int r1 = r0 + 8;
#pragma unroll
    for (int j = 0; j < 8; j++) {
        const int col = (j >> 1) * 16 + (j & 1) * 8 + (lane & 3) * 2;
        const float b0 = bias_s[col], b1 = bias_s[col + 1];
        __half2 v0 = __floats2half2_rn((acc[j][0] + b0) * qs, (acc[j][1] + b1) * qs);
        __half2 v1 = __floats2half2_rn((acc[j][2] + b0) * qs, (acc[j][3] + b1) * qs);
        *(__half2*)&outp[(size_t)r0 * Dd + col] = v0;
        *(__half2*)&outp[(size_t)r1 * Dd + col] = v1;
    }
}

// ---------------------------------------------------------------------------
// Kernel 2: flash attention. 4 warps x m32/warp (halves redundant K/V
// ldmatrix traffic vs 8 x m16 — the smem crossbar was the binding pipe).
// cp.async double-buffered K/V; f16x2 exp2; ones-mma row sums.
// ---------------------------------------------------------------------------
#define NT (Ww / 64)   // 32 KV tiles

__global__ __launch_bounds__(128, 2) void attn_kernel(
    const float* __restrict__ mask, float* __restrict__ out)
{
    __shared__ alignas(16) unsigned char smbuf[36864 + 512];
    __half (*Qs)[72] = reinterpret_cast<__half(*)[72]>(smbuf + 18432);
    float*  mskbuf   = reinterpret_cast<float*>(smbuf + 36864);
    float (*Os)[65]  = reinterpret_cast<float(*)[65]>(smbuf);

    const int bh = blockIdx.y;
    const int qt = blockIdx.x;
    const int n  = bh / Hh;
    const int h  = bh % Hh;
    const int tid  = threadIdx.x;
    const int warp = tid >> 5;
    const int lane = tid & 31;
    const int m0   = warp * 32;          // 32 query rows per warp
    const int tq   = lane >> 3;
    const int li   = lane & 7;

    const __half* Qp = g_Q + ((size_t)bh * Ww + qt * 128) * Dd;
    const __half* Kp = g_K + (size_t)bh * Ww * Dd;
    const __half* Vp = g_V + (size_t)bh * Ww * Dd;
    const float*  mp = mask + (size_t)n * Ww;

    // issue tile 0 -> buf0 (128 threads x 8 cp16 = 16 KB)
    {
        uint32_t kb = (uint32_t)__cvta_generic_to_shared(smbuf);
        uint32_t vb = kb + 9216;
#pragma unroll
        for (int i = 0; i < 4; i++) {
            const int fi = tid + i * 128;
            const int r = fi >> 3, c8 = (fi & 7) << 3;
            cp16(kb + (r * 72 + c8) * 2, Kp + (size_t)r * Dd + c8);
            cp16(vb + (r * 72 + c8) * 2, Vp + (size_t)r * Dd + c8);
        }
        if (tid < 16)
            cp16((uint32_t)__cvta_generic_to_shared(&mskbuf[tid * 4]), mp + tid * 4);
        cp_commit();
    }

    // stage Q (into buf1 region) and build fragments
#pragma unroll
    for (int i = 0; i < 8; i++) {
        const int fi = tid + i * 128;
        const int r = fi >> 3, c8 = (fi & 7) << 3;
        *(uint4*)&Qs[r][c8] = *(const uint4*)&Qp[(size_t)r * Dd + c8];
    }
    __syncthreads();

    uint32_t qf[2][4][4];
#pragma unroll
    for (int hh = 0; hh < 2; hh++)
#pragma unroll
        for (int kk = 0; kk < 4; kk++) {
            const int row = m0 + hh * 16 + (tq & 1) * 8 + li;
            const int col = kk * 16 + (tq >> 1) * 8;
            uint32_t a = (uint32_t)__cvta_generic_to_shared(&Qs[row][col]);
            ldsm_x4(qf[hh][kk][0], qf[hh][kk][1], qf[hh][kk][2], qf[hh][kk][3], a);
        }

    float ctx[2][8][4];
#pragma unroll
    for (int hh = 0; hh < 2; hh++)
#pragma unroll
        for (int j = 0; j < 8; j++)
#pragma unroll
            for (int c = 0; c < 4; c++) ctx[hh][j][c] = 0.f;
    float lacc[2][4] = {{0.f,0.f,0.f,0.f},{0.f,0.f,0.f,0.f}};

    for (int kt = 0; kt < NT; kt++) {
        const int cur = kt & 1;
        const __half (*Ks)[72] = reinterpret_cast<const __half(*)[72]>(smbuf + cur * 18432);
        const __half (*Vs)[72] = reinterpret_cast<const __half(*)[72]>(smbuf + cur * 18432 + 9216);
        const float* msk = mskbuf + cur * 64;

        cp_wait0();
        __syncthreads();

        // prefetch next tile into the other buffer
        if (kt + 1 < NT) {
            const int nb = cur ^ 1;
            const __half* Kn = Kp + (size_t)(kt + 1) * 64 * Dd;
            const __half* Vn = Vp + (size_t)(kt + 1) * 64 * Dd;
            uint32_t kb = (uint32_t)__cvta_generic_to_shared(smbuf) + nb * 18432;
            uint32_t vb = kb + 9216;
#pragma unroll
            for (int i = 0; i < 4; i++) {
                const int fi = tid + i * 128;
                const int r = fi >> 3, c8 = (fi & 7) << 3;
                cp16(kb + (r * 72 + c8) * 2, Kn + (size_t)r * Dd + c8);
                cp16(vb + (r * 72 + c8) * 2, Vn + (size_t)r * Dd + c8);
            }
            if (tid < 16)
                cp16((uint32_t)__cvta_generic_to_shared(&mskbuf[nb * 64 + tid * 4]),
                     mp + (kt + 1) * 64 + tid * 4);
        }
        cp_commit();

        // ---- S = Q K^T : K frags loaded ONCE per kk, used by both halves ----
        float SA[2][8][4];
#pragma unroll
        for (int hh = 0; hh < 2; hh++)
#pragma unroll
            for (int j = 0; j < 8; j++)
#pragma unroll
                for (int c = 0; c < 4; c++) SA[hh][j][c] = 0.f;

#pragma unroll
        for (int kk = 0; kk < 4; kk++) {
            uint32_t b[16];
#pragma unroll
            for (int p = 0; p < 4; p++) {
                const int row = (p * 2 + (tq >> 1)) * 8 + li;
                const int col = kk * 16 + (tq & 1) * 8;
                uint32_t a = (uint32_t)__cvta_generic_to_shared(&Ks[row][col]);
                ldsm_x4(b[p * 4], b[p * 4 + 1], b[p * 4 + 2], b[p * 4 + 3], a);
            }
#pragma unroll
            for (int hh = 0; hh < 2; hh++)
#pragma unroll
                for (int j = 0; j < 8; j++) {
                    const int base = (j >> 1) * 4 + (j & 1) * 2;
                    mma16816(SA[hh][j], qf[hh][kk], b[base], b[base + 1]);
                }
        }

        // ---- P = exp2(s + mask*log2e) -> fp16 A-fragments; ones-mma row sums ----
        uint32_t pf[2][4][4];
#pragma unroll
        for (int hh = 0; hh < 2; hh++)
#pragma unroll
            for (int kk = 0; kk < 4; kk++) {
                const int j0 = 2 * kk, j1 = 2 * kk + 1;
                float2 mk0 = *(float2*)&msk[j0 * 8 + (lane & 3) * 2];
                float2 mk1 = *(float2*)&msk[j1 * 8 + (lane & 3) * 2];
                pf[hh][kk][0] = ex2h2(pack_h2(fmaf(mk0.x, LOG2E, SA[hh][j0][0]),
                                              fmaf(mk0.y, LOG2E, SA[hh][j0][1])));
                pf[hh][kk][1] = ex2h2(pack_h2(fmaf(mk0.x, LOG2E, SA[hh][j0][2]),
                                              fmaf(mk0.y, LOG2E, SA[hh][j0][3])));
                pf[hh][kk][2] = ex2h2(pack_h2(fmaf(mk1.x, LOG2E, SA[hh][j1][0]),
                                              fmaf(mk1.y, LOG2E, SA[hh][j1][1])));
                pf[hh][kk][3] = ex2h2(pack_h2(fmaf(mk1.x, LOG2E, SA[hh][j1][2]),
                                              fmaf(mk1.y, LOG2E, SA[hh][j1][3])));
                mma16816(lacc[hh], pf[hh][kk], ONES_H2, ONES_H2);
            }

        // ---- ctx += P V : V frags loaded ONCE per kk, used by both halves ----
#pragma unroll
        for (int kk = 0; kk < 4; kk++) {
            uint32_t b[16];
#pragma unroll
            for (int p = 0; p < 4; p++) {
                const int rowk = kk * 16 + (tq & 1) * 8 + li;
                const int cold = (p * 2 + (tq >> 1)) * 8;
                uint32_t a = (uint32_t)__cvta_generic_to_shared(&Vs[rowk][cold]);
                ldsm_x4_t(b[p * 4], b[p * 4 + 1], b[p * 4 + 2], b[p * 4 + 3], a);
            }
#pragma unroll
            for (int hh = 0; hh < 2; hh++)
#pragma unroll
                for (int j = 0; j < 8; j++) {
                    const int base = (j >> 1) * 4 + (j & 1) * 2;
                    mma16816(ctx[hh][j], pf[hh][kk], b[base], b[base + 1]);
                }
        }
    }

    // normalize + transpose through smem
    __syncthreads();
#pragma unroll
    for (int hh = 0; hh < 2; hh++) {
        const float inv0 = 1.f / lacc[hh][0];
        const float inv1 = 1.f / lacc[hh][2];
        const int r0 = m0 + hh * 16 + (lane >> 2);
        const int r1 = r0 + 8;
#pragma unroll
        for (int j = 0; j < 8; j++) {
            const int col = j * 8 + (lane & 3) * 2;
            Os[r0][col]     = ctx[hh][j][0] * inv0;
            Os[r0][col + 1] = ctx[hh][j][1] * inv0;
            Os[r1][col]     = ctx[hh][j][2] * inv1;
            Os[r1][col + 1] = ctx[hh][j][3] * inv1;
        }
    }
    __syncthreads();

    // out[n, h*64+d, qt*128 + m]: float2 over m
    float* outp = out + ((size_t)n * Cc + h * 64) * Ww + qt * 128;
    for (int idx = tid; idx < 64 * 64; idx += 128) {
        const int d = idx >> 6, mp2 = (idx & 63) << 1;
        float2 v = make_float2(Os[mp2][d], Os[mp2 + 1][d]);
        *(float2*)&outp[(size_t)d * Ww + mp2] = v;
    }
}

extern "C" void kernel_launch(void* const* d_in, const int* in_sizes, int n_in,
                              void* d_out, int out_size)
{
    const float* x    = (const float*)d_in[0];
    const float* mask = (const float*)d_in[1];
    const float* wq   = (const float*)d_in[2];
    const float* bq   = (const float*)d_in[3];
    const float* wk   = (const float*)d_in[4];
    const float* bk   = (const float*)d_in[5];
    const float* wv   = (const float*)d_in[6];
    const float* bv   = (const float*)d_in[7];
    float* out = (float*)d_out;

    dim3 g1(Ww / 128, CPG / 64, Nn * Gg * 3);
    qkv_kernel<<<g1, 256>>>(x, wq, bq, wk, bk, wv, bv);

    dim3 g2(Ww / 128, Nn * Hh);
    attn_kernel<<<g2, 128>>>(mask, out);
}

// round 15
// speedup vs baseline: 1.3659x; 1.3659x over previous
#include <cuda_runtime.h>
#include <cuda_fp16.h>
#include <math.h>
#include <stdint.h>

#define Nn  4
#define Cc  768
#define Ww  2048
#define Hh  12
#define Dd  64
#define Gg  4
#define CPG 192
#define LOG2E 1.4426950408889634f
#define ONES_H2 0x3C003C00u   // half2(1.0, 1.0)

// fp16 scratch for projected Q/K/V in [n, h, w, d] layout. Q pre-scaled by
// 0.125 * log2(e) so attention scores are directly in log2 domain.
__device__ __half g_Q[(size_t)Nn*Hh*Ww*Dd];
__device__ __half g_K[(size_t)Nn*Hh*Ww*Dd];
__device__ __half g_V[(size_t)Nn*Hh*Ww*Dd];

// ---------------- shared PTX helpers ----------------
__device__ __forceinline__ void ldsm_x4(uint32_t& r0, uint32_t& r1,
                                        uint32_t& r2, uint32_t& r3, uint32_t a) {
    asm volatile("ldmatrix.sync.aligned.m8n8.x4.shared.b16 {%0,%1,%2,%3}, [%4];\n"
                 : "=r"(r0), "=r"(r1), "=r"(r2), "=r"(r3) : "r"(a));
}
__device__ __forceinline__ void ldsm_x4_t(uint32_t& r0, uint32_t& r1,
                                          uint32_t& r2, uint32_t& r3, uint32_t a) {
    asm volatile("ldmatrix.sync.aligned.m8n8.x4.trans.shared.b16 {%0,%1,%2,%3}, [%4];\n"
                 : "=r"(r0), "=r"(r1), "=r"(r2), "=r"(r3) : "r"(a));
}
__device__ __forceinline__ void mma16816(float* c, const uint32_t* a,
                                         uint32_t b0, uint32_t b1) {
    asm volatile("mma.sync.aligned.m16n8k16.row.col.f32.f16.f16.f32 "
                 "{%0,%1,%2,%3}, {%4,%5,%6,%7}, {%8,%9}, {%0,%1,%2,%3};\n"
                 : "+f"(c[0]), "+f"(c[1]), "+f"(c[2]), "+f"(c[3])
                 : "r"(a[0]), "r"(a[1]), "r"(a[2]), "r"(a[3]), "r"(b0), "r"(b1));
}
__device__ __forceinline__ uint32_t pack_h2(float lo, float hi) {
    uint32_t r;
    asm("cvt.rn.f16x2.f32 %0, %1, %2;" : "=r"(r) : "f"(hi), "f"(lo));
    return r;
}
__device__ __forceinline__ uint32_t ex2h2(uint32_t x) {
    uint32_t y;
    asm("ex2.approx.f16x2 %0, %1;" : "=r"(y) : "r"(x));
    return y;
}
__device__ __forceinline__ void cp16(uint32_t dst, const void* src) {
    asm volatile("cp.async.cg.shared.global [%0], [%1], 16;\n" :: "r"(dst), "l"(src));
}
__device__ __forceinline__ void cp_commit() {
    asm volatile("cp.async.commit_group;\n");
}
__device__ __forceinline__ void cp_wait0() {
    asm volatile("cp.async.wait_group 0;\n");
}

// ---------------------------------------------------------------------------
// Kernel 1: grouped 1x1 conv as HMMA GEMM (unchanged, proven).
// ---------------------------------------------------------------------------
__global__ __launch_bounds__(256) void qkv_kernel(
    const float* __restrict__ x,
    const float* __restrict__ wq, const float* __restrict__ bq,
    const float* __restrict__ wk, const float* __restrict__ bk,
    const float* __restrict__ wv, const float* __restrict__ bv)
{
    __shared__ alignas(16) __half Xs[2][32][136];
    __shared__ alignas(16) __half Ws[2][64][40];
    __shared__ float bias_s[64];

    const int wt = blockIdx.x;
    const int ot = blockIdx.y;
    const int z  = blockIdx.z;
    const int t  = z % 3;
    const int ng = z / 3;
    const int n  = ng >> 2, g = ng & 3;

    const float* W = (t == 0) ? wq : (t == 1) ? wk : wv;
    const float* B = (t == 0) ? bq : (t == 1) ? bk : bv;
    __half* dst    = (t == 0) ? g_Q : (t == 1) ? g_K : g_V;

    const int tid  = threadIdx.x;
    const int warp = tid >> 5;
    const int lane = tid & 31;
    const int tq   = lane >> 3;
    const int li   = lane & 7;
    const int m0w  = warp * 16;

    const int cgbase = g * CPG + ot * 64;
    const int h = cgbase >> 6;
    const int w0 = wt * 128;
    const float* Wg = W + (size_t)g * CPG * CPG + (size_t)(ot * 64) * CPG;
    const float* Xg = x + ((size_t)n * Cc + g * CPG) * Ww;

    if (tid < 64) bias_s[tid] = B[cgbase + tid];

    const int xc  = tid >> 3;
    const int xw  = (tid & 7) * 16;
    const int woc = tid >> 2;
    const int wc  = (tid & 3) * 8;

    float4 xr[4], wr[2];
    {
        const float* src = &Xg[(size_t)xc * Ww + w0 + xw];
        xr[0] = *(const float4*)&src[0];
        xr[1] = *(const float4*)&src[4];
        xr[2] = *(const float4*)&src[8];
        xr[3] = *(const float4*)&src[12];
        const float* ws = &Wg[(size_t)woc * CPG + wc];
        wr[0] = *(const float4*)&ws[0];
        wr[1] = *(const float4*)&ws[4];
    }

    float acc[8][4];
#pragma unroll
    for (int j = 0; j < 8; j++)
#pragma unroll
        for (int c = 0; c < 4; c++) acc[j][c] = 0.f;

    for (int it = 0; it < 6; it++) {
        const int cur = it & 1;
        {
            __align__(16) __half2 hh[8];
            hh[0] = __floats2half2_rn(xr[0].x, xr[0].y);
            hh[1] = __floats2half2_rn(xr[0].z, xr[0].w);
            hh[2] = __floats2half2_rn(xr[1].x, xr[1].y);
            hh[3] = __floats2half2_rn(xr[1].z, xr[1].w);
            hh[4] = __floats2half2_rn(xr[2].x, xr[2].y);
            hh[5] = __floats2half2_rn(xr[2].z, xr[2].w);
            hh[6] = __floats2half2_rn(xr[3].x, xr[3].y);
            hh[7] = __floats2half2_rn(xr[3].z, xr[3].w);
            *(uint4*)&Xs[cur][xc][xw]     = ((uint4*)hh)[0];
            *(uint4*)&Xs[cur][xc][xw + 8] = ((uint4*)hh)[1];
            __align__(16) __half2 wh[4];
            wh[0] = __floats2half2_rn(wr[0].x, wr[0].y);
            wh[1] = __floats2half2_rn(wr[0].z, wr[0].w);
            wh[2] = __floats2half2_rn(wr[1].x, wr[1].y);
            wh[3] = __floats2half2_rn(wr[1].z, wr[1].w);
            *(uint4*)&Ws[cur][woc][wc] = *(uint4*)wh;
        }
        __syncthreads();
        if (it + 1 < 6) {
            const int k0 = (it + 1) * 32;
            const float* src = &Xg[(size_t)(k0 + xc) * Ww + w0 + xw];
            xr[0] = *(const float4*)&src[0];
            xr[1] = *(const float4*)&src[4];
            xr[2] = *(const float4*)&src[8];
            xr[3] = *(const float4*)&src[12];
            const float* ws = &Wg[(size_t)woc * CPG + (it + 1) * 32 + wc];
            wr[0] = *(const float4*)&ws[0];
            wr[1] = *(const float4*)&ws[4];
        }

#pragma unroll
        for (int kk = 0; kk < 2; kk++) {
            uint32_t af[4];
            {
                const int row = kk * 16 + (tq >> 1) * 8 + li;
                const int col = m0w + (tq & 1) * 8;
                uint32_t a = (uint32_t)__cvta_generic_to_shared(&Xs[cur][row][col]);
                ldsm_x4_t(af[0], af[1], af[2], af[3], a);
            }
            uint32_t b[16];
#pragma unroll
            for (int p = 0; p < 4; p++) {
                const int row = (p * 2 + (tq >> 1)) * 8 + li;
                const int col = kk * 16 + (tq & 1) * 8;
                uint32_t a = (uint32_t)__cvta_generic_to_shared(&Ws[cur][row][col]);
                ldsm_x4(b[p * 4], b[p * 4 + 1], b[p * 4 + 2], b[p * 4 + 3], a);
            }
#pragma unroll
            for (int j = 0; j < 8; j++) {
                const int base = (j >> 1) * 4 + (j & 1) * 2;
                mma16816(acc[j], af, b[base], b[base + 1]);
            }
        }
    }

    const float qs = (t == 0) ? (0.125f * LOG2E) : 1.0f;
    __half* outp = dst + (((size_t)n * Hh + h) * Ww + w0) * Dd;
    const int r0 = m0w + (lane >> 2);
    const int r1 = r0 + 8;
#pragma unroll
    for (int j = 0; j < 8; j++) {
        const int col = (j >> 1) * 16 + (j & 1) * 8 + (lane & 3) * 2;
        const float b0 = bias_s[col], b1 = bias_s[col + 1];
        __half2 v0 = __floats2half2_rn((acc[j][0] + b0) * qs, (acc[j][1] + b1) * qs);
        __half2 v1 = __floats2half2_rn((acc[j][2] + b0) * qs, (acc[j][3] + b1) * qs);
        *(__half2*)&outp[(size_t)r0 * Dd + col] = v0;
        *(__half2*)&outp[(size_t)r1 * Dd + col] = v1;
    }
}

// ---------------------------------------------------------------------------
// Kernel 2: flash attention. BM=64, 8 warps = 4(m16) x 2(n32): each warp
// loads K/V fragments ONLY for its 32-key half (halves smem crossbar traffic
// at 16 warps/SM and ~120 regs). Partial ctx/lacc reduced across the n-pair
// once at the end through smem. cp.async double-buffered; f16x2 exp2;
// ones-mma row sums.
// ---------------------------------------------------------------------------
#define NT (Ww / 64)   // 32 KV tiles

__global__ __launch_bounds__(256, 2) void attn_kernel(
    const float* __restrict__ mask, float* __restrict__ out)
{
    // [0,18432): buf0 K[64][72]h | V[64][72]h
    // [18432,36864): buf1 K|V (Qs[64][72]h aliases during prologue)
    // [36864,37376): msk[2][64] f32 ; [37376,37632): Lred[64] f32
    // After the loop: Cred[64][68] f32 aliases buf0; Os[64][65] f32 aliases buf1.
    __shared__ alignas(16) unsigned char smbuf[37632];
    __half (*Qs)[72]  = reinterpret_cast<__half(*)[72]>(smbuf + 18432);
    float*  mskbuf    = reinterpret_cast<float*>(smbuf + 36864);
    float*  Lred      = reinterpret_cast<float*>(smbuf + 37376);
    float (*Cred)[68] = reinterpret_cast<float(*)[68]>(smbuf);
    float (*Os)[65]   = reinterpret_cast<float(*)[65]>(smbuf + 18432);

    const int bh = blockIdx.y;            // n*H + h
    const int qt = blockIdx.x;            // 32 q-tiles of 64
    const int n  = bh / Hh;
    const int h  = bh % Hh;
    const int tid  = threadIdx.x;
    const int warp = tid >> 5;
    const int lane = tid & 31;
    const int wm   = warp & 3;            // m position (4)
    const int wn   = warp >> 2;           // n half (2)
    const int m0   = wm * 16;
    const int n0   = wn * 32;             // this warp's key window in the tile
    const int tq   = lane >> 3;
    const int li   = lane & 7;

    const __half* Qp = g_Q + ((size_t)bh * Ww + qt * 64) * Dd;
    const __half* Kp = g_K + (size_t)bh * Ww * Dd;
    const __half* Vp = g_V + (size_t)bh * Ww * Dd;
    const float*  mp = mask + (size_t)n * Ww;

    // issue tile 0 -> buf0 (K,V 8KB each = 512+512 chunks; 2 each per thread)
    {
        uint32_t kb = (uint32_t)__cvta_generic_to_shared(smbuf);
        uint32_t vb = kb + 9216;
#pragma unroll
        for (int i = 0; i < 2; i++) {
            const int fi = tid + i * 256;
            const int r = fi >> 3, c8 = (fi & 7) << 3;
            cp16(kb + (r * 72 + c8) * 2, Kp + (size_t)r * Dd + c8);
            cp16(vb + (r * 72 + c8) * 2, Vp + (size_t)r * Dd + c8);
        }
        if (tid < 16)
            cp16((uint32_t)__cvta_generic_to_shared(&mskbuf[tid * 4]), mp + tid * 4);
        cp_commit();
    }

    // stage Q (64x64 halves into buf1 region) and build fragments
#pragma unroll
    for (int i = 0; i < 2; i++) {
        const int fi = tid + i * 256;
        const int r = fi >> 3, c8 = (fi & 7) << 3;
        *(uint4*)&Qs[r][c8] = *(const uint4*)&Qp[(size_t)r * Dd + c8];
    }
    __syncthreads();

    uint32_t qf[4][4];
#pragma unroll
    for (int kk = 0; kk < 4; kk++) {
        const int row = m0 + (tq & 1) * 8 + li;
        const int col = kk * 16 + (tq >> 1) * 8;
        uint32_t a = (uint32_t)__cvta_generic_to_shared(&Qs[row][col]);
        ldsm_x4(qf[kk][0], qf[kk][1], qf[kk][2], qf[kk][3], a);
    }

    float ctx[8][4];
#pragma unroll
    for (int j = 0; j < 8; j++)
#pragma unroll
        for (int c = 0; c < 4; c++) ctx[j][c] = 0.f;
    float lacc[4] = {0.f, 0.f, 0.f, 0.f};

    for (int kt = 0; kt < NT; kt++) {
        const int cur = kt & 1;
        const __half (*Ks)[72] = reinterpret_cast<const __half(*)[72]>(smbuf + cur * 18432);
        const __half (*Vs)[72] = reinterpret_cast<const __half(*)[72]>(smbuf + cur * 18432 + 9216);
        const float* msk = mskbuf + cur * 64;

        cp_wait0();
        __syncthreads();

        if (kt + 1 < NT) {
            const int nb = cur ^ 1;
            const __half* Kn = Kp + (size_t)(kt + 1) * 64 * Dd;
            const __half* Vn = Vp + (size_t)(kt + 1) * 64 * Dd;
            uint32_t kb = (uint32_t)__cvta_generic_to_shared(smbuf) + nb * 18432;
            uint32_t vb = kb + 9216;
#pragma unroll
            for (int i = 0; i < 2; i++) {
                const int fi = tid + i * 256;
                const int r = fi >> 3, c8 = (fi & 7) << 3;
                cp16(kb + (r * 72 + c8) * 2, Kn + (size_t)r * Dd + c8);
                cp16(vb + (r * 72 + c8) * 2, Vn + (size_t)r * Dd + c8);
            }
            if (tid < 16)
                cp16((uint32_t)__cvta_generic_to_shared(&mskbuf[nb * 64 + tid * 4]),
                     mp + (kt + 1) * 64 + tid * 4);
        }
        cp_commit();

        // ---- S = Q K^T over this warp's 32-key window ----
        float SA[4][4];
#pragma unroll
        for (int j = 0; j < 4; j++)
#pragma unroll
            for (int c = 0; c < 4; c++) SA[j][c] = 0.f;

#pragma unroll
        for (int kk = 0; kk < 4; kk++) {
            uint32_t b[8];
#pragma unroll
            for (int p = 0; p < 2; p++) {
                const int row = n0 + (p * 2 + (tq >> 1)) * 8 + li;
                const int col = kk * 16 + (tq & 1) * 8;
                uint32_t a = (uint32_t)__cvta_generic_to_shared(&Ks[row][col]);
                ldsm_x4(b[p * 4], b[p * 4 + 1], b[p * 4 + 2], b[p * 4 + 3], a);
            }
#pragma unroll
            for (int j = 0; j < 4; j++) {
                const int base = (j >> 1) * 4 + (j & 1) * 2;
                mma16816(SA[j], qf[kk], b[base], b[base + 1]);
            }
        }

        // ---- P = exp2(s + mask*log2e) -> fp16 A-fragments; ones-mma sums ----
        uint32_t pf[2][4];
#pragma unroll
        for (int kk = 0; kk < 2; kk++) {
            const int j0 = 2 * kk, j1 = 2 * kk + 1;
            float2 mk0 = *(float2*)&msk[n0 + j0 * 8 + (lane & 3) * 2];
            float2 mk1 = *(float2*)&msk[n0 + j1 * 8 + (lane & 3) * 2];
            pf[kk][0] = ex2h2(pack_h2(fmaf(mk0.x, LOG2E, SA[j0][0]),
                                      fmaf(mk0.y, LOG2E, SA[j0][1])));
            pf[kk][1] = ex2h2(pack_h2(fmaf(mk0.x, LOG2E, SA[j0][2]),
                                      fmaf(mk0.y, LOG2E, SA[j0][3])));
            pf[kk][2] = ex2h2(pack_h2(fmaf(mk1.x, LOG2E, SA[j1][0]),
                                      fmaf(mk1.y, LOG2E, SA[j1][1])));
            pf[kk][3] = ex2h2(pack_h2(fmaf(mk1.x, LOG2E, SA[j1][2]),
                                      fmaf(mk1.y, LOG2E, SA[j1][3])));
            mma16816(lacc, pf[kk], ONES_H2, ONES_H2);
        }

        // ---- ctx += P V over this warp's 32 keys ----
#pragma unroll
        for (int kk = 0; kk < 2; kk++) {
            uint32_t b[16];
#pragma unroll
            for (int p = 0; p < 4; p++) {
                const int rowk = n0 + kk * 16 + (tq & 1) * 8 + li;
                const int cold = (p * 2 + (tq >> 1)) * 8;
                uint32_t a = (uint32_t)__cvta_generic_to_shared(&Vs[rowk][cold]);
                ldsm_x4_t(b[p * 4], b[p * 4 + 1], b[p * 4 + 2], b[p * 4 + 3], a);
            }
#pragma unroll
            for (int j = 0; j < 8; j++) {
                const int base = (j >> 1) * 4 + (j & 1) * 2;
                mma16816(ctx[j], pf[kk], b[base], b[base + 1]);
            }
        }
    }

    // ---- reduce partial ctx/lacc across the n-warp pair ----
    const int r0 = m0 + (lane >> 2);
    const int r1 = r0 + 8;
    __syncthreads();
    if (wn == 1) {
#pragma unroll
        for (int j = 0; j < 8; j++) {
            const int col = j * 8 + (lane & 3) * 2;
            Cred[r0][col]     = ctx[j][0];
            Cred[r0][col + 1] = ctx[j][1];
            Cred[r1][col]     = ctx[j][2];
            Cred[r1][col + 1] = ctx[j][3];
        }
        if ((lane & 3) == 0) { Lred[r0] = lacc[0]; Lred[r1] = lacc[2]; }
    }
    __syncthreads();
    if (wn == 0) {
        const float inv0 = 1.f / (lacc[0] + Lred[r0]);
        const float inv1 = 1.f / (lacc[2] + Lred[r1]);
#pragma unroll
        for (int j = 0; j < 8; j++) {
            const int col = j * 8 + (lane & 3) * 2;
            Os[r0][col]     = (ctx[j][0] + Cred[r0][col])     * inv0;
            Os[r0][col + 1] = (ctx[j][1] + Cred[r0][col + 1]) * inv0;
            Os[r1][col]     = (ctx[j][2] + Cred[r1][col])     * inv1;
            Os[r1][col + 1] = (ctx[j][3] + Cred[r1][col + 1]) * inv1;
        }
    }
    __syncthreads();

    // out[n, h*64+d, qt*64 + m]: float2 over m
    float* outp = out + ((size_t)n * Cc + h * 64) * Ww + qt * 64;
    for (int idx = tid; idx < 64 * 32; idx += 256) {
        const int d = idx >> 5, mp2 = (idx & 31) << 1;
        float2 v = make_float2(Os[mp2][d], Os[mp2 + 1][d]);
        *(float2*)&outp[(size_t)d * Ww + mp2] = v;
    }
}

extern "C" void kernel_launch(void* const* d_in, const int* in_sizes, int n_in,
                              void* d_out, int out_size)
{
    const float* x    = (const float*)d_in[0];
    const float* mask = (const float*)d_in[1];
    const float* wq   = (const float*)d_in[2];
    const float* bq   = (const float*)d_in[3];
    const float* wk   = (const float*)d_in[4];
    const float* bk   = (const float*)d_in[5];
    const float* wv   = (const float*)d_in[6];
    const float* bv   = (const float*)d_in[7];
    float* out = (float*)d_out;

    dim3 g1(Ww / 128, CPG / 64, Nn * Gg * 3);
    qkv_kernel<<<g1, 256>>>(x, wq, bq, wk, bk, wv, bv);

    dim3 g2(Ww / 64, Nn * Hh);
    attn_kernel<<<g2, 256>>>(mask, out);
}

// round 17
// speedup vs baseline: 1.5144x; 1.1087x over previous
#include <cuda_runtime.h>
#include <cuda_fp16.h>
#include <math.h>
#include <stdint.h>

#define Nn  4
#define Cc  768
#define Ww  2048
#define Hh  12
#define Dd  64
#define Gg  4
#define CPG 192
#define LOG2E 1.4426950408889634f
#define ONES_H2 0x3C003C00u   // half2(1.0, 1.0)

// fp16 scratch for projected Q/K/V in [n, h, w, d] layout. Q pre-scaled by
// 0.125 * log2(e) so attention scores are directly in log2 domain.
__device__ __half g_Q[(size_t)Nn*Hh*Ww*Dd];
__device__ __half g_K[(size_t)Nn*Hh*Ww*Dd];
__device__ __half g_V[(size_t)Nn*Hh*Ww*Dd];

// ---------------- shared PTX helpers ----------------
__device__ __forceinline__ void ldsm_x4(uint32_t& r0, uint32_t& r1,
                                        uint32_t& r2, uint32_t& r3, uint32_t a) {
    asm volatile("ldmatrix.sync.aligned.m8n8.x4.shared.b16 {%0,%1,%2,%3}, [%4];\n"
                 : "=r"(r0), "=r"(r1), "=r"(r2), "=r"(r3) : "r"(a));
}
__device__ __forceinline__ void ldsm_x4_t(uint32_t& r0, uint32_t& r1,
                                          uint32_t& r2, uint32_t& r3, uint32_t a) {
    asm volatile("ldmatrix.sync.aligned.m8n8.x4.trans.shared.b16 {%0,%1,%2,%3}, [%4];\n"
                 : "=r"(r0), "=r"(r1), "=r"(r2), "=r"(r3) : "r"(a));
}
__device__ __forceinline__ void mma16816(float* c, const uint32_t* a,
                                         uint32_t b0, uint32_t b1) {
    asm volatile("mma.sync.aligned.m16n8k16.row.col.f32.f16.f16.f32 "
                 "{%0,%1,%2,%3}, {%4,%5,%6,%7}, {%8,%9}, {%0,%1,%2,%3};\n"
                 : "+f"(c[0]), "+f"(c[1]), "+f"(c[2]), "+f"(c[3])
                 : "r"(a[0]), "r"(a[1]), "r"(a[2]), "r"(a[3]), "r"(b0), "r"(b1));
}
__device__ __forceinline__ uint32_t pack_h2(float lo, float hi) {
    uint32_t r;
    asm("cvt.rn.f16x2.f32 %0, %1, %2;" : "=r"(r) : "f"(hi), "f"(lo));
    return r;
}
__device__ __forceinline__ uint32_t ex2h2(uint32_t x) {
    uint32_t y;
    asm("ex2.approx.f16x2 %0, %1;" : "=r"(y) : "r"(x));
    return y;
}
__device__ __forceinline__ void cp16(uint32_t dst, const void* src) {
    asm volatile("cp.async.cg.shared.global [%0], [%1], 16;\n" :: "r"(dst), "l"(src));
}
__device__ __forceinline__ void cp_commit() {
    asm volatile("cp.async.commit_group;\n");
}
__device__ __forceinline__ void cp_wait0() {
    asm volatile("cp.async.wait_group 0;\n");
}

// ---------------------------------------------------------------------------
// Kernel 1: FUSED grouped 1x1 conv for q,k,v. Each block stages its x k-chunk
// into smem ONCE and runs HMMA against all three weight sets (x L2 traffic /3).
// M=128 w, N=64 oc (one head) per weight set, K=192.
// ---------------------------------------------------------------------------
__global__ __launch_bounds__(256) void qkv_kernel(
    const float* __restrict__ x,
    const float* __restrict__ wq, const float* __restrict__ bq,
    const float* __restrict__ wk, const float* __restrict__ bk,
    const float* __restrict__ wv, const float* __restrict__ bv)
{
    __shared__ alignas(16) __half Xs[2][32][136];      // 17408 B
    __shared__ alignas(16) __half Ws[2][3][64][40];    // 30720 B
    __shared__ float bias_s[3][64];                    //   768 B  (total 48896)

    const int wt = blockIdx.x;                 // 16 w-tiles of 128
    const int ot = blockIdx.y;                 // 3 oc-tiles of 64
    const int ng = blockIdx.z;                 // 16
    const int n  = ng >> 2, g = ng & 3;

    const float* Wp[3] = {wq, wk, wv};
    const float* Bp[3] = {bq, bk, bv};
    __half* Dp[3]      = {g_Q, g_K, g_V};

    const int tid  = threadIdx.x;
    const int warp = tid >> 5;
    const int lane = tid & 31;
    const int tq   = lane >> 3;
    const int li   = lane & 7;
    const int m0w  = warp * 16;

    const int cgbase = g * CPG + ot * 64;
    const int h = cgbase >> 6;
    const int w0 = wt * 128;
    const float* Xg = x + ((size_t)n * Cc + g * CPG) * Ww;

    if (tid < 64) {
        bias_s[0][tid] = bq[cgbase + tid];
        bias_s[1][tid] = bk[cgbase + tid];
        bias_s[2][tid] = bv[cgbase + tid];
    }

    const int xc  = tid >> 3;
    const int xw  = (tid & 7) * 16;
    const int woc = tid >> 2;
    const int wc  = (tid & 3) * 8;
    const size_t wgoff = (size_t)g * CPG * CPG + (size_t)(ot * 64 + woc) * CPG + wc;

    float4 xr[4], wr[3][2];
    {
        const float* src = &Xg[(size_t)xc * Ww + w0 + xw];
        xr[0] = *(const float4*)&src[0];
        xr[1] = *(const float4*)&src[4];
        xr[2] = *(const float4*)&src[8];
        xr[3] = *(const float4*)&src[12];
#pragma unroll
        for (int t = 0; t < 3; t++) {
            const float* ws = Wp[t] + wgoff;
            wr[t][0] = *(const float4*)&ws[0];
            wr[t][1] = *(const float4*)&ws[4];
        }
    }

    float acc[3][8][4];
#pragma unroll
    for (int t = 0; t < 3; t++)
#pragma unroll
        for (int j = 0; j < 8; j++)
#pragma unroll
            for (int c = 0; c < 4; c++) acc[t][j][c] = 0.f;

    for (int it = 0; it < 6; it++) {
        const int cur = it & 1;
        {
            __align__(16) __half2 hh[8];
            hh[0] = __floats2half2_rn(xr[0].x, xr[0].y);
            hh[1] = __floats2half2_rn(xr[0].z, xr[0].w);
            hh[2] = __floats2half2_rn(xr[1].x, xr[1].y);
            hh[3] = __floats2half2_rn(xr[1].z, xr[1].w);
            hh[4] = __floats2half2_rn(xr[2].x, xr[2].y);
            hh[5] = __floats2half2_rn(xr[2].z, xr[2].w);
            hh[6] = __floats2half2_rn(xr[3].x, xr[3].y);
            hh[7] = __floats2half2_rn(xr[3].z, xr[3].w);
            *(uint4*)&Xs[cur][xc][xw]     = ((uint4*)hh)[0];
            *(uint4*)&Xs[cur][xc][xw + 8] = ((uint4*)hh)[1];
#pragma unroll
            for (int t = 0; t < 3; t++) {
                __align__(16) __half2 wh[4];
                wh[0] = __floats2half2_rn(wr[t][0].x, wr[t][0].y);
                wh[1] = __floats2half2_rn(wr[t][0].z, wr[t][0].w);
                wh[2] = __floats2half2_rn(wr[t][1].x, wr[t][1].y);
                wh[3] = __floats2half2_rn(wr[t][1].z, wr[t][1].w);
                *(uint4*)&Ws[cur][t][woc][wc] = *(uint4*)wh;
            }
        }
        __syncthreads();
        if (it + 1 < 6) {
            const int k0 = (it + 1) * 32;
            const float* src = &Xg[(size_t)(k0 + xc) * Ww + w0 + xw];
            xr[0] = *(const float4*)&src[0];
            xr[1] = *(const float4*)&src[4];
            xr[2] = *(const float4*)&src[8];
            xr[3] = *(const float4*)&src[12];
#pragma unroll
            for (int t = 0; t < 3; t++) {
                const float* ws = Wp[t] + wgoff + k0;
                wr[t][0] = *(const float4*)&ws[0];
                wr[t][1] = *(const float4*)&ws[4];
            }
        }

#pragma unroll
        for (int kk = 0; kk < 2; kk++) {
            uint32_t af[4];
            {
                const int row = kk * 16 + (tq >> 1) * 8 + li;
                const int col = m0w + (tq & 1) * 8;
                uint32_t a = (uint32_t)__cvta_generic_to_shared(&Xs[cur][row][col]);
                ldsm_x4_t(af[0], af[1], af[2], af[3], a);
            }
#pragma unroll
            for (int t = 0; t < 3; t++) {
                uint32_t b[16];
#pragma unroll
                for (int p = 0; p < 4; p++) {
                    const int row = (p * 2 + (tq >> 1)) * 8 + li;
                    const int col = kk * 16 + (tq & 1) * 8;
                    uint32_t a = (uint32_t)__cvta_generic_to_shared(&Ws[cur][t][row][col]);
                    ldsm_x4(b[p * 4], b[p * 4 + 1], b[p * 4 + 2], b[p * 4 + 3], a);
                }
#pragma unroll
                for (int j = 0; j < 8; j++) {
                    const int base = (j >> 1) * 4 + (j & 1) * 2;
                    mma16816(acc[t][j], af, b[base], b[base + 1]);
                }
            }
        }
    }

    const int r0 = m0w + (lane >> 2);
    const int r1 = r0 + 8;
#pragma unroll
    for (int t = 0; t < 3; t++) {
        const float qs = (t == 0) ? (0.125f * LOG2E) : 1.0f;
        __half* outp = Dp[t] + (((size_t)n * Hh + h) * Ww + w0) * Dd;
#pragma unroll
        for (int j = 0; j < 8; j++) {
            const int col = (j >> 1) * 16 + (j & 1) * 8 + (lane & 3) * 2;
            const float b0 = bias_s[t][col], b1 = bias_s[t][col + 1];
            __half2 v0 = __floats2half2_rn((acc[t][j][0] + b0) * qs, (acc[t][j][1] + b1) * qs);
            __half2 v1 = __floats2half2_rn((acc[t][j][2] + b0) * qs, (acc[t][j][3] + b1) * qs);
            *(__half2*)&outp[(size_t)r0 * Dd + col] = v0;
            *(__half2*)&outp[(size_t)r1 * Dd + col] = v1;
        }
    }
}

// ---------------------------------------------------------------------------
// Kernel 2: flash attention (R12-proven). 8 warps x m16, cp.async double-
// buffered K/V, f16x2 exp2, ones-mma row sums.
// ---------------------------------------------------------------------------
#define NT (Ww / 64)   // 32 KV tiles

__global__ __launch_bounds__(256, 2) void attn_kernel(
    const float* __restrict__ mask, float* __restrict__ out)
{
    __shared__ alignas(16) unsigned char smbuf[36864 + 512];
    __half (*Qs)[72] = reinterpret_cast<__half(*)[72]>(smbuf + 18432);
    float*  mskbuf   = reinterpret_cast<float*>(smbuf + 36864);
    float (*Os)[65]  = reinterpret_cast<float(*)[65]>(smbuf);

    const int bh = blockIdx.y;
    const int qt = blockIdx.x;
    const int n  = bh / Hh;
    const int h  = bh % Hh;
    const int tid  = threadIdx.x;
    const int warp = tid >> 5;
    const int lane = tid & 31;
    const int m0   = warp * 16;
    const int tq   = lane >> 3;
    const int li   = lane & 7;

    const __half* Qp = g_Q + ((size_t)bh * Ww + qt * 128) * Dd;
    const __half* Kp = g_K + (size_t)bh * Ww * Dd;
    const __half* Vp = g_V + (size_t)bh * Ww * Dd;
    const float*  mp = mask + (size_t)n * Ww;

    // issue tile 0 -> buf0
    {
        const int id0 = tid, id1 = tid + 256;
        const int r0 = id0 >> 3, c80 = (id0 & 7) << 3;
        const int r1 = id1 >> 3, c81 = (id1 & 7) << 3;
        uint32_t kb = (uint32_t)__cvta_generic_to_shared(smbuf);
        uint32_t vb = kb + 9216;
        cp16(kb + (r0 * 72 + c80) * 2, Kp + (size_t)r0 * Dd + c80);
        cp16(kb + (r1 * 72 + c81) * 2, Kp + (size_t)r1 * Dd + c81);
        cp16(vb + (r0 * 72 + c80) * 2, Vp + (size_t)r0 * Dd + c80);
        cp16(vb + (r1 * 72 + c81) * 2, Vp + (size_t)r1 * Dd + c81);
        if (tid < 16)
            cp16((uint32_t)__cvta_generic_to_shared(&mskbuf[tid * 4]), mp + tid * 4);
        cp_commit();
    }

    // stage Q (into buf1 region) and build fragments
    for (int i = 0; i < 4; i++) {
        const int fi = tid + i * 256;
        const int r = fi >> 3, c8 = (fi & 7) << 3;
        *(uint4*)&Qs[r][c8] = *(const uint4*)&Qp[(size_t)r * Dd + c8];
    }
    __syncthreads();

    uint32_t qf[4][4];
#pragma unroll
    for (int kk = 0; kk < 4; kk++) {
        const int row = m0 + (tq & 1) * 8 + li;
        const int col = kk * 16 + (tq >> 1) * 8;
        uint32_t a = (uint32_t)__cvta_generic_to_shared(&Qs[row][col]);
        ldsm_x4(qf[kk][0], qf[kk][1], qf[kk][2], qf[kk][3], a);
    }

    float ctx[8][4];
#pragma unroll
    for (int j = 0; j < 8; j++)
#pragma unroll
        for (int c = 0; c < 4; c++) ctx[j][c] = 0.f;
    float lacc[4] = {0.f, 0.f, 0.f, 0.f};

    for (int kt = 0; kt < NT; kt++) {
        const int cur = kt & 1;
        const __half (*Ks)[72] = reinterpret_cast<const __half(*)[72]>(smbuf + cur * 18432);
        const __half (*Vs)[72] = reinterpret_cast<const __half(*)[72]>(smbuf + cur * 18432 + 9216);
        const float* msk = mskbuf + cur * 64;

        cp_wait0();
        __syncthreads();

        if (kt + 1 < NT) {
            const int nb = cur ^ 1;
            const __half* Kn = Kp + (size_t)(kt + 1) * 64 * Dd;
            const __half* Vn = Vp + (size_t)(kt + 1) * 64 * Dd;
            const int id0 = tid, id1 = tid + 256;
            const int r0 = id0 >> 3, c80 = (id0 & 7) << 3;
            const int r1 = id1 >> 3, c81 = (id1 & 7) << 3;
            uint32_t kb = (uint32_t)__cvta_generic_to_shared(smbuf) + nb * 18432;
            uint32_t vb = kb + 9216;
            cp16(kb + (r0 * 72 + c80) * 2, Kn + (size_t)r0 * Dd + c80);
            cp16(kb + (r1 * 72 + c81) * 2, Kn + (size_t)r1 * Dd + c81);
            cp16(vb + (r0 * 72 + c80) * 2, Vn + (size_t)r0 * Dd + c80);
            cp16(vb + (r1 * 72 + c81) * 2, Vn + (size_t)r1 * Dd + c81);
            if (tid < 16)
                cp16((uint32_t)__cvta_generic_to_shared(&mskbuf[nb * 64 + tid * 4]),
                     mp + (kt + 1) * 64 + tid * 4);
        }
        cp_commit();

        // ---- S = Q K^T ----
        float SA[8][4];
#pragma unroll
        for (int j = 0; j < 8; j++)
#pragma unroll
            for (int c = 0; c < 4; c++) SA[j][c] = 0.f;

#pragma unroll
        for (int kk = 0; kk < 4; kk++) {
            uint32_t b[16];
#pragma unroll
            for (int p = 0; p < 4; p++) {
                const int row = (p * 2 + (tq >> 1)) * 8 + li;
                const int col = kk * 16 + (tq & 1) * 8;
                uint32_t a = (uint32_t)__cvta_generic_to_shared(&Ks[row][col]);
                ldsm_x4(b[p * 4], b[p * 4 + 1], b[p * 4 + 2], b[p * 4 + 3], a);
            }
#pragma unroll
            for (int j = 0; j < 8; j++) {
                const int base = (j >> 1) * 4 + (j & 1) * 2;
                mma16816(SA[j], qf[kk], b[base], b[base + 1]);
            }
        }

        // ---- P = exp2(s + mask*log2e): pack f32->f16x2, one MUFU per pair ----
        uint32_t pf[4][4];
#pragma unroll
        for (int kk = 0; kk < 4; kk++) {
            const int j0 = 2 * kk, j1 = 2 * kk + 1;
            float2 mk0 = *(float2*)&msk[j0 * 8 + (lane & 3) * 2];
            float2 mk1 = *(float2*)&msk[j1 * 8 + (lane & 3) * 2];
            pf[kk][0] = ex2h2(pack_h2(fmaf(mk0.x, LOG2E, SA[j0][0]),
                                      fmaf(mk0.y, LOG2E, SA[j0][1])));
            pf[kk][1] = ex2h2(pack_h2(fmaf(mk0.x, LOG2E, SA[j0][2]),
                                      fmaf(mk0.y, LOG2E, SA[j0][3])));
            pf[kk][2] = ex2h2(pack_h2(fmaf(mk1.x, LOG2E, SA[j1][0]),
                                      fmaf(mk1.y, LOG2E, SA[j1][1])));
            pf[kk][3] = ex2h2(pack_h2(fmaf(mk1.x, LOG2E, SA[j1][2]),
                                      fmaf(mk1.y, LOG2E, SA[j1][3])));
            mma16816(lacc, pf[kk], ONES_H2, ONES_H2);
        }

        // ---- ctx += P V ----
#pragma unroll
        for (int kk = 0; kk < 4; kk++) {
            uint32_t b[16];
#pragma unroll
            for (int p = 0; p < 4; p++) {
                const int rowk = kk * 16 + (tq & 1) * 8 + li;
                const int cold = (p * 2 + (tq >> 1)) * 8;
                uint32_t a = (uint32_t)__cvta_generic_to_shared(&Vs[rowk][cold]);
                ldsm_x4_t(b[p * 4], b[p * 4 + 1], b[p * 4 + 2], b[p * 4 + 3], a);
            }
#pragma unroll
            for (int j = 0; j < 8; j++) {
                const int base = (j >> 1) * 4 + (j & 1) * 2;
                mma16816(ctx[j], pf[kk], b[base], b[base + 1]);
            }
        }
    }

    // lacc[0] / lacc[2] are the full row sums (no shuffles)
    const float inv0 = 1.f / lacc[0];
    const float inv1 = 1.f / lacc[2];

    // normalize + transpose through smem
    __syncthreads();
    {
        const int r0 = m0 + (lane >> 2);
        const int r1 = r0 + 8;
#pragma unroll
        for (int j = 0; j < 8; j++) {
            const int col = j * 8 + (lane & 3) * 2;
            Os[r0][col]     = ctx[j][0] * inv0;
            Os[r0][col + 1] = ctx[j][1] * inv0;
            Os[r1][col]     = ctx[j][2] * inv1;
            Os[r1][col + 1] = ctx[j][3] * inv1;
        }
    }
    __syncthreads();

    float* outp = out + ((size_t)n * Cc + h * 64) * Ww + qt * 128;
    for (int idx = tid; idx < 128 * 64; idx += 256) {
        const int d = idx >> 7, m = idx & 127;
        outp[(size_t)d * Ww + m] = Os[m][d];
    }
}

extern "C" void kernel_launch(void* const* d_in, const int* in_sizes, int n_in,
                              void* d_out, int out_size)
{
    const float* x    = (const float*)d_in[0];
    const float* mask = (const float*)d_in[1];
    const float* wq   = (const float*)d_in[2];
    const float* bq   = (const float*)d_in[3];
    const float* wk   = (const float*)d_in[4];
    const float* bk   = (const float*)d_in[5];
    const float* wv   = (const float*)d_in[6];
    const float* bv   = (const float*)d_in[7];
    float* out = (float*)d_out;

    dim3 g1(Ww / 128, CPG / 64, Nn * Gg);
    qkv_kernel<<<g1, 256>>>(x, wq, bq, wk, bk, wv, bv);

    dim3 g2(Ww / 128, Nn * Hh);
    attn_kernel<<<g2, 256>>>(mask, out);
}